// round 1
// baseline (speedup 1.0000x reference)
#include <cuda_runtime.h>
#include <cuda_bf16.h>

#define BATCH   16
#define CIN     256
#define COUT    256
#define HH      32
#define WW      32
#define HW      1024
#define NE      8
#define CO_TILE 8
#define CI_CHUNK 8
#define HALO    34

__device__ int g_decisions[BATCH];

// ---------------------------------------------------------------------------
// Kernel 1: global-avg-pool -> linear router -> argmax  (one block per batch)
// ---------------------------------------------------------------------------
__global__ void router_kernel(const float* __restrict__ x,
                              const float* __restrict__ wc,
                              const float* __restrict__ bc) {
    int b    = blockIdx.x;
    int tid  = threadIdx.x;
    int warp = tid >> 5;
    int lane = tid & 31;

    __shared__ float sPooled[CIN];
    __shared__ float sLog[NE];

    const float* xb = x + (size_t)b * CIN * HW;

    // Each warp reduces channels warp, warp+8, ... (coalesced within channel)
    for (int ci = warp; ci < CIN; ci += 8) {
        const float* p = xb + (size_t)ci * HW;
        float s = 0.f;
        #pragma unroll 4
        for (int k = lane; k < HW; k += 32) s += p[k];
        #pragma unroll
        for (int o = 16; o > 0; o >>= 1) s += __shfl_xor_sync(0xffffffffu, s, o);
        if (lane == 0) sPooled[ci] = s * (1.0f / HW);
    }
    __syncthreads();

    if (warp == 0) {
        if (lane < NE) {
            const float* w = wc + lane * CIN;
            float s = 0.f;
            #pragma unroll 8
            for (int k = 0; k < CIN; k++) s += sPooled[k] * w[k];
            sLog[lane] = s + bc[lane];
        }
        __syncwarp();
        if (lane == 0) {
            float best = sLog[0];
            int   bi   = 0;
            #pragma unroll
            for (int e = 1; e < NE; e++) {
                if (sLog[e] > best) { best = sLog[e]; bi = e; }
            }
            g_decisions[b] = bi;
        }
    }
}

// ---------------------------------------------------------------------------
// Kernel 2: 3x3 SAME conv for distinct (batch, expert) pairs, broadcast-write
// Grid: (1, COUT/CO_TILE, BATCH*NE).  Block: 256 threads.
// Each thread owns 4 pixels (tid, tid+256, tid+512, tid+768) x 8 out-channels.
// ---------------------------------------------------------------------------
__global__ __launch_bounds__(256, 2)
void conv_kernel(const float* __restrict__ x,
                 const float* __restrict__ we,
                 const float* __restrict__ be,
                 float* __restrict__ out) {
    const int z   = blockIdx.z;
    const int i   = z & (BATCH - 1);   // input batch
    const int e   = z >> 4;            // expert
    const int co0 = blockIdx.y * CO_TILE;
    const int tid = threadIdx.x;

    __shared__ int   sDec[BATCH];
    __shared__ float sX[CI_CHUNK][HALO * HALO];
    __shared__ float sW[CO_TILE * CI_CHUNK * 9];

    if (tid < BATCH) sDec[tid] = g_decisions[tid];
    __syncthreads();

    bool need = false;
    #pragma unroll
    for (int j = 0; j < BATCH; j++) need |= (sDec[j] == e);
    if (!need) return;   // block-uniform exit: skip unused experts entirely

    float acc[CO_TILE][4];
    #pragma unroll
    for (int co = 0; co < CO_TILE; co++)
        #pragma unroll
        for (int k = 0; k < 4; k++) acc[co][k] = 0.f;

    const float* xb = x  + (size_t)i * CIN * HW;
    const float* wb = we + ((size_t)e * COUT + co0) * (size_t)CIN * 9;

    int px[4], py[4];
    #pragma unroll
    for (int k = 0; k < 4; k++) {
        int p = tid + k * 256;
        py[k] = p >> 5;
        px[k] = p & 31;
    }

    for (int c0 = 0; c0 < CIN; c0 += CI_CHUNK) {
        __syncthreads();  // protect smem reuse from previous iteration

        // --- cooperative load of X chunk with 1-pixel zero halo ---
        for (int idx = tid; idx < CI_CHUNK * HALO * HALO; idx += 256) {
            int c   = idx / (HALO * HALO);
            int rem = idx - c * (HALO * HALO);
            int r   = rem / HALO;
            int col = rem - r * HALO;
            int gy  = r - 1, gx = col - 1;
            float v = 0.f;
            if ((unsigned)gy < 32u && (unsigned)gx < 32u)
                v = xb[(size_t)(c0 + c) * HW + gy * WW + gx];
            sX[c][rem] = v;
        }
        // --- cooperative load of weights: 8 co x 8 ci x 9 taps ---
        for (int idx = tid; idx < CO_TILE * CI_CHUNK * 9; idx += 256) {
            int co  = idx / (CI_CHUNK * 9);
            int rem = idx - co * (CI_CHUNK * 9);
            sW[idx] = wb[(size_t)co * CIN * 9 + (size_t)c0 * 9 + rem];
        }
        __syncthreads();

        #pragma unroll 1
        for (int c = 0; c < CI_CHUNK; c++) {
            // load 4 pixel neighborhoods (36 regs), reused across 8 co
            float xv[4][9];
            #pragma unroll
            for (int k = 0; k < 4; k++) {
                #pragma unroll
                for (int t = 0; t < 9; t++)
                    xv[k][t] = sX[c][(py[k] + t / 3) * HALO + px[k] + (t % 3)];
            }
            #pragma unroll
            for (int co = 0; co < CO_TILE; co++) {
                float wr[9];
                #pragma unroll
                for (int t = 0; t < 9; t++)
                    wr[t] = sW[(co * CI_CHUNK + c) * 9 + t];   // broadcast LDS
                #pragma unroll
                for (int k = 0; k < 4; k++)
                    #pragma unroll
                    for (int t = 0; t < 9; t++)
                        acc[co][k] = fmaf(xv[k][t], wr[t], acc[co][k]);
            }
        }
    }

    // --- epilogue: bias + relu, write every output block using this expert ---
    float bias[CO_TILE];
    #pragma unroll
    for (int co = 0; co < CO_TILE; co++) bias[co] = be[e * COUT + co0 + co];

    #pragma unroll 1
    for (int j = 0; j < BATCH; j++) {
        if (sDec[j] != e) continue;
        float* ob = out + ((size_t)(j * BATCH + i) * COUT + co0) * HW;
        #pragma unroll
        for (int co = 0; co < CO_TILE; co++) {
            #pragma unroll
            for (int k = 0; k < 4; k++) {
                float v = acc[co][k] + bias[co];
                ob[(size_t)co * HW + tid + k * 256] = fmaxf(v, 0.f);
            }
        }
    }
}

// ---------------------------------------------------------------------------
extern "C" void kernel_launch(void* const* d_in, const int* in_sizes, int n_in,
                              void* d_out, int out_size) {
    const float* x  = (const float*)d_in[0];
    const float* wc = (const float*)d_in[1];
    const float* bc = (const float*)d_in[2];
    const float* we = (const float*)d_in[3];
    const float* be = (const float*)d_in[4];
    float* out = (float*)d_out;

    router_kernel<<<BATCH, 256>>>(x, wc, bc);

    dim3 grid(1, COUT / CO_TILE, BATCH * NE);
    conv_kernel<<<grid, 256>>>(x, we, be, out);
}